// round 4
// baseline (speedup 1.0000x reference)
#include <cuda_runtime.h>
#include <math.h>

// Problem constants
#define Bn 2
#define Cc 2
#define Ff 1024
#define Ww 1024
#define Hh 4
#define Dd 256
#define EF 4096
#define Ll 15
#define NBn 3
#define BC 4              // B*C
#define FW (Ff*Ww)        // 1048576

// ---------------- scratch (device globals; no allocations) ----------------
__device__ float g_h [BC*FW];
__device__ float g_t0[BC*FW];
__device__ float g_t1[BC*FW];
__device__ float g_q [BC*FW];
__device__ float g_k [BC*FW];
__device__ float g_v [BC*FW];
__device__ float g_s [16*1024*1024];   // attention scores [bc,h,W,W]
__device__ float g_u [BC*EF*Ww];       // FFN intermediate

__device__ __forceinline__ float gelu_f(float x) {
    return 0.5f * x * (1.0f + erff(x * 0.70710678118654752f));
}

// ---------------- batched SGEMM ----------------
// C[m,n] = scale * sum_k a(m,k)*b(k,n) (+bias[m]) (optional GELU)
// TA==0: a(m,k)=A[m*lda+k]   TA==1: a(m,k)=A[k*lda+m]
// TB==0: b(k,n)=B[k*ldb+n]   TB==1: b(k,n)=B[n*ldb+k]
// batching: z -> (bb=z/heads, hh=z%heads); A offset (bb%aMod)*aSB + hh*aSH, etc.
// Requires M%128==0, N%128==0, K%8==0 (all shapes here satisfy this).
template<int TA, int TB, int DOGELU, int HASBIAS>
__global__ __launch_bounds__(256) void gemm_k(
    const float* __restrict__ Ag, const float* __restrict__ Bg, float* __restrict__ Cg,
    const float* __restrict__ biasg,
    int M, int N, int K, int lda, int ldb, int ldc,
    int heads, int aMod,
    long long aSB, long long aSH, long long bSB, long long bSH,
    long long cSB, long long cSH, long long biasSB, float scale)
{
    const int z  = blockIdx.z;
    const int bb = z / heads, hh = z % heads;
    const float* A = Ag + (long long)(bb % aMod) * aSB + (long long)hh * aSH;
    const float* B = Bg + (long long)bb * bSB + (long long)hh * bSH;
    float*       C = Cg + (long long)bb * cSB + (long long)hh * cSH;
    const int m0 = blockIdx.y * 128;
    const int n0 = blockIdx.x * 128;
    const int tid = threadIdx.x;

    __shared__ float As[8][128];
    __shared__ float Bs[8][128];

    int a_r, a_c, b_r, b_c;
    if (TA == 0) { a_r = tid >> 1; a_c = (tid & 1) * 4; }
    else         { a_r = tid >> 5; a_c = (tid & 31) * 4; }
    if (TB == 0) { b_r = tid >> 5; b_c = (tid & 31) * 4; }
    else         { b_r = tid >> 1; b_c = (tid & 1) * 4; }

    float acc[8][8];
    #pragma unroll
    for (int i = 0; i < 8; i++)
        #pragma unroll
        for (int j = 0; j < 8; j++) acc[i][j] = 0.f;

    const int tx = tid & 15, ty = tid >> 4;

    float4 pa, pb;
    if (TA == 0) pa = *(const float4*)&A[(long long)(m0 + a_r) * lda + a_c];
    else         pa = *(const float4*)&A[(long long)a_r * lda + m0 + a_c];
    if (TB == 0) pb = *(const float4*)&B[(long long)b_r * ldb + n0 + b_c];
    else         pb = *(const float4*)&B[(long long)(n0 + b_r) * ldb + b_c];

    for (int k0 = 0; k0 < K; k0 += 8) {
        if (TA == 0) { As[a_c+0][a_r]=pa.x; As[a_c+1][a_r]=pa.y; As[a_c+2][a_r]=pa.z; As[a_c+3][a_r]=pa.w; }
        else         { *(float4*)&As[a_r][a_c] = pa; }
        if (TB == 0) { *(float4*)&Bs[b_r][b_c] = pb; }
        else         { Bs[b_c+0][b_r]=pb.x; Bs[b_c+1][b_r]=pb.y; Bs[b_c+2][b_r]=pb.z; Bs[b_c+3][b_r]=pb.w; }
        __syncthreads();

        const int k1 = k0 + 8;
        if (k1 < K) {
            if (TA == 0) pa = *(const float4*)&A[(long long)(m0 + a_r) * lda + k1 + a_c];
            else         pa = *(const float4*)&A[(long long)(k1 + a_r) * lda + m0 + a_c];
            if (TB == 0) pb = *(const float4*)&B[(long long)(k1 + b_r) * ldb + n0 + b_c];
            else         pb = *(const float4*)&B[(long long)(n0 + b_r) * ldb + k1 + b_c];
        }
        #pragma unroll
        for (int kk = 0; kk < 8; kk++) {
            float ar[8], br[8];
            *(float4*)&ar[0] = *(const float4*)&As[kk][ty*8];
            *(float4*)&ar[4] = *(const float4*)&As[kk][ty*8+4];
            *(float4*)&br[0] = *(const float4*)&Bs[kk][tx*8];
            *(float4*)&br[4] = *(const float4*)&Bs[kk][tx*8+4];
            #pragma unroll
            for (int i = 0; i < 8; i++)
                #pragma unroll
                for (int j = 0; j < 8; j++)
                    acc[i][j] = fmaf(ar[i], br[j], acc[i][j]);
        }
        __syncthreads();
    }

    const float* bp = HASBIAS ? (biasg + (long long)(bb % aMod) * biasSB) : nullptr;
    #pragma unroll
    for (int i = 0; i < 8; i++) {
        const int m = m0 + ty*8 + i;
        const float bv = HASBIAS ? bp[m] : 0.f;
        float out[8];
        #pragma unroll
        for (int j = 0; j < 8; j++) {
            float v = acc[i][j] * scale + bv;
            if (DOGELU) v = gelu_f(v);
            out[j] = v;
        }
        *(float4*)&C[(long long)m*ldc + n0 + tx*8    ] = *(float4*)&out[0];
        *(float4*)&C[(long long)m*ldc + n0 + tx*8 + 4] = *(float4*)&out[4];
    }
}

// ---------------- conv 3x3 (pad 1), optional GELU epilogue ----------------
__global__ __launch_bounds__(256) void conv3x3_k(
    const float* __restrict__ x, float* __restrict__ y,
    const float* __restrict__ wt, const float* __restrict__ bs, int dogelu)
{
    const int t = blockIdx.x * 256 + threadIdx.x;      // over B*C*F*W = 4M
    const int wc = t & 1023;
    const int f  = (t >> 10) & 1023;
    const int co = (t >> 20) & 1;
    const int bb = t >> 21;
    float s = bs[co];
    #pragma unroll
    for (int ci = 0; ci < Cc; ci++) {
        const float* xp = x + ((size_t)(bb*Cc + ci)) * FW;
        const float* wp = wt + (co*Cc + ci) * 9;
        #pragma unroll
        for (int ky = 0; ky < 3; ky++) {
            const int ff = f + ky - 1;
            if ((unsigned)ff < (unsigned)Ff) {
                const float* row = xp + (size_t)ff * Ww;
                #pragma unroll
                for (int kx = 0; kx < 3; kx++) {
                    const int ww = wc + kx - 1;
                    if ((unsigned)ww < (unsigned)Ww) s = fmaf(row[ww], wp[ky*3+kx], s);
                }
            }
        }
    }
    if (dogelu) s = gelu_f(s);
    y[t] = s;
}

// ---------------- conv 1x7 along W (pad 3) ----------------
__global__ __launch_bounds__(256) void conv1x7_k(
    const float* __restrict__ x, float* __restrict__ y,
    const float* __restrict__ wt, const float* __restrict__ bs)
{
    const int t = blockIdx.x * 256 + threadIdx.x;      // over 4M
    const int wc = t & 1023;
    const int f  = (t >> 10) & 1023;
    const int co = (t >> 20) & 1;
    const int bb = t >> 21;
    float s = bs[co];
    #pragma unroll
    for (int ci = 0; ci < Cc; ci++) {
        const float* row = x + ((size_t)(bb*Cc + ci) * Ff + f) * Ww;
        const float* wp  = wt + (co*Cc + ci) * 7;
        #pragma unroll
        for (int j = 0; j < 7; j++) {
            const int ww = wc + j - 3;
            if ((unsigned)ww < (unsigned)Ww) s = fmaf(row[ww], wp[j], s);
        }
    }
    y[t] = s;
}

// ---------------- interleaved RoPE, in place on [bc, F, W] ----------------
__global__ __launch_bounds__(256) void rope_k(float* __restrict__ p)
{
    const int t = blockIdx.x * 256 + threadIdx.x;      // over BC*(F/2)*W = 2M
    const int wc = t & 1023;
    const int fp = (t >> 10) & 511;                    // pair index within F/2
    const int bc = t >> 19;
    const int tt = fp & 127;                           // (f % D)/2, D=256
    const float inv = expf(-(float)tt * (9.2103403719761836f / 128.f)); // 10000^(-2t/D)
    const float ang = (float)wc * inv;
    float sn, cn; sincosf(ang, &sn, &cn);
    const size_t base = ((size_t)bc * Ff + 2*fp) * Ww + wc;
    const float x0 = p[base], x1 = p[base + Ww];
    p[base]      = x0*cn - x1*sn;
    p[base + Ww] = x1*cn + x0*sn;
}

// ---------------- row softmax over last axis (rows of 1024) ----------------
__global__ __launch_bounds__(256) void softmax_k(float* __restrict__ sp)
{
    float* p = sp + (size_t)blockIdx.x * Ww;
    const int t = threadIdx.x, lane = t & 31, wid = t >> 5;
    float4 v = ((const float4*)p)[t];
    float mx = fmaxf(fmaxf(v.x, v.y), fmaxf(v.z, v.w));
    #pragma unroll
    for (int o = 16; o > 0; o >>= 1) mx = fmaxf(mx, __shfl_xor_sync(0xffffffffu, mx, o));
    __shared__ float red[8];
    if (lane == 0) red[wid] = mx;
    __syncthreads();
    mx = red[0];
    #pragma unroll
    for (int i = 1; i < 8; i++) mx = fmaxf(mx, red[i]);
    __syncthreads();
    v.x = expf(v.x - mx); v.y = expf(v.y - mx); v.z = expf(v.z - mx); v.w = expf(v.w - mx);
    float sm = v.x + v.y + v.z + v.w;
    #pragma unroll
    for (int o = 16; o > 0; o >>= 1) sm += __shfl_xor_sync(0xffffffffu, sm, o);
    if (lane == 0) red[wid] = sm;
    __syncthreads();
    sm = red[0] + red[1] + red[2] + red[3] + red[4] + red[5] + red[6] + red[7];
    const float r = 1.f / sm;
    v.x *= r; v.y *= r; v.z *= r; v.w *= r;
    ((float4*)p)[t] = v;
}

// ---------------- residual + LayerNorm over F axis, h <- LN(h+z) ----------------
__global__ __launch_bounds__(512) void lnres_k(
    float* __restrict__ h, const float* __restrict__ z,
    const float* __restrict__ g, const float* __restrict__ b)
{
    const int tx = threadIdx.x, ty = threadIdx.y;
    const int wc = blockIdx.x * 32 + tx;
    const int bc = blockIdx.y;
    const int c  = bc & 1;
    float* hp = h + (size_t)bc * FW + wc;
    const float* zp = z + (size_t)bc * FW + wc;
    float sum = 0.f, sq = 0.f;
    for (int f = ty; f < Ff; f += 16) {
        const float v = hp[(size_t)f * Ww] + zp[(size_t)f * Ww];
        sum += v; sq += v * v;
    }
    __shared__ float s1[16][32], s2[16][32];
    __shared__ float smu[32], srs[32];
    s1[ty][tx] = sum; s2[ty][tx] = sq;
    __syncthreads();
    if (ty == 0) {
        float a = 0.f, q = 0.f;
        #pragma unroll
        for (int r = 0; r < 16; r++) { a += s1[r][tx]; q += s2[r][tx]; }
        const float mu = a * (1.f / Ff);
        const float var = q * (1.f / Ff) - mu * mu;
        smu[tx] = mu; srs[tx] = rsqrtf(var + 1e-5f);
    }
    __syncthreads();
    const float mu = smu[tx], rs = srs[tx];
    for (int f = ty; f < Ff; f += 16) {
        const float v = hp[(size_t)f * Ww] + zp[(size_t)f * Ww];
        hp[(size_t)f * Ww] = (v - mu) * rs * g[c*Ff + f] + b[c*Ff + f];
    }
}

// ---------------- 2-channel mix (1x1 conv / output projection) ----------------
__global__ __launch_bounds__(256) void chanmix_k(
    const float* __restrict__ in, float* __restrict__ out,
    const float* __restrict__ m, const float* __restrict__ bs)
{
    const int t = blockIdx.x * 256 + threadIdx.x;      // over B*2*FW = 4M
    const int pos = t & (FW - 1);
    const int co  = (t >> 20) & 1;
    const int bb  = t >> 21;
    float s = bs ? bs[co] : 0.f;
    s = fmaf(in[(size_t)(bb*Cc + 0) * FW + pos], m[co*Cc + 0], s);
    s = fmaf(in[(size_t)(bb*Cc + 1) * FW + pos], m[co*Cc + 1], s);
    out[t] = s;
}

// ---------------- launch ----------------
extern "C" void kernel_launch(void* const* d_in, const int* in_sizes, int n_in,
                              void* d_out, int out_size)
{
    (void)in_sizes; (void)n_in; (void)out_size;
    const float* x       = (const float*)d_in[0];
    const float* enc_c1w = (const float*)d_in[1];
    const float* enc_c1b = (const float*)d_in[2];
    const float* enc_c2w = (const float*)d_in[3];
    const float* enc_c2b = (const float*)d_in[4];
    const float* enc_nw  = (const float*)d_in[5];
    const float* enc_nb  = (const float*)d_in[6];
    const float* qw  = (const float*)d_in[7];
    const float* qb  = (const float*)d_in[8];
    const float* qcw = (const float*)d_in[9];
    const float* qcb = (const float*)d_in[10];
    const float* kw  = (const float*)d_in[11];
    const float* kb  = (const float*)d_in[12];
    const float* kcw = (const float*)d_in[13];
    const float* kcb = (const float*)d_in[14];
    const float* vw  = (const float*)d_in[15];
    const float* vb  = (const float*)d_in[16];
    const float* vcw = (const float*)d_in[17];
    const float* vcb = (const float*)d_in[18];
    const float* ow  = (const float*)d_in[19];
    const float* ob  = (const float*)d_in[20];
    const float* ocw = (const float*)d_in[21];
    const float* ocb = (const float*)d_in[22];
    const float* n1w = (const float*)d_in[23];
    const float* n1b = (const float*)d_in[24];
    const float* f1w = (const float*)d_in[25];
    const float* f1b = (const float*)d_in[26];
    const float* f2w = (const float*)d_in[27];
    const float* f2b = (const float*)d_in[28];
    const float* n2w = (const float*)d_in[29];
    const float* n2b = (const float*)d_in[30];
    const float* out_w = (const float*)d_in[31];

    float *h, *t0, *t1, *q, *k, *v, *s, *u;
    cudaGetSymbolAddress((void**)&h,  g_h);
    cudaGetSymbolAddress((void**)&t0, g_t0);
    cudaGetSymbolAddress((void**)&t1, g_t1);
    cudaGetSymbolAddress((void**)&q,  g_q);
    cudaGetSymbolAddress((void**)&k,  g_k);
    cudaGetSymbolAddress((void**)&v,  g_v);
    cudaGetSymbolAddress((void**)&s,  g_s);
    cudaGetSymbolAddress((void**)&u,  g_u);

    const int EW = 16384;        // blocks for 4M-element elementwise kernels
    const dim3 LN_G(Ww/32, BC), LN_B(32, 16);
    const long long DW = (long long)Dd * Ww;
    const int BIGMOD = 1 << 24;

    cudaMemcpyAsync(h, x, sizeof(float) * (size_t)BC * FW, cudaMemcpyDeviceToDevice, 0);

    // per-(b,c) weight linear: C[M,W] = Wt[M,K] @ X[K,W] + bias, batch z = bc, weight by c
    auto WGEMM = [&](const float* A, const float* Bx, float* Cx, const float* bias,
                     int M, int K, bool gelu) {
        dim3 grid(Ww/128, M/128, BC);
        if (gelu)
            gemm_k<0,0,1,1><<<grid,256>>>(A, Bx, Cx, bias, M, Ww, K, K, Ww, Ww,
                1, Cc, (long long)M*K, 0, (long long)K*Ww, 0, (long long)M*Ww, 0,
                (long long)M, 1.f);
        else
            gemm_k<0,0,0,1><<<grid,256>>>(A, Bx, Cx, bias, M, Ww, K, K, Ww, Ww,
                1, Cc, (long long)M*K, 0, (long long)K*Ww, 0, (long long)M*Ww, 0,
                (long long)M, 1.f);
    };

    // --------- FrameEncoder: 3 ResBlocks ---------
    for (int nb = 0; nb < NBn; nb++) {
        conv3x3_k<<<EW,256>>>(h,  t0, enc_c1w + nb*Cc*Cc*9, enc_c1b + nb*Cc, 1);
        conv3x3_k<<<EW,256>>>(t0, t1, enc_c2w + nb*Cc*Cc*9, enc_c2b + nb*Cc, 0);
        lnres_k<<<LN_G,LN_B>>>(h, t1, enc_nw + nb*Cc*Ff, enc_nb + nb*Cc*Ff);
    }

    // --------- Transformer layers ---------
    for (int l = 0; l < Ll; l++) {
        const long long lwF = (long long)l * Cc * Ff * Ff;
        // Q
        WGEMM(qw + lwF, h, t0, qb + l*Cc*Ff, Ff, Ff, false);
        conv1x7_k<<<EW,256>>>(t0, q, qcw + l*Cc*Cc*7, qcb + l*Cc);
        rope_k<<<8192,256>>>(q);
        // K
        WGEMM(kw + lwF, h, t0, kb + l*Cc*Ff, Ff, Ff, false);
        conv1x7_k<<<EW,256>>>(t0, k, kcw + l*Cc*Cc*7, kcb + l*Cc);
        rope_k<<<8192,256>>>(k);
        // V
        WGEMM(vw + lwF, h, t0, vb + l*Cc*Ff, Ff, Ff, false);
        conv1x7_k<<<EW,256>>>(t0, v, vcw + l*Cc*Cc*7, vcb + l*Cc);

        // scores = Q^T K / sqrt(F), per (bc, head): [W,W], K-dim = D
        gemm_k<1,0,0,0><<<dim3(8,8,16),256>>>(q, k, s, nullptr,
            Ww, Ww, Dd, Ww, Ww, Ww, Hh, BIGMOD,
            (long long)FW, DW, (long long)FW, DW, 4LL*FW, (long long)FW, 0, 0.03125f);
        softmax_k<<<16*1024,256>>>(s);
        // attnout[d,i] = sum_j V[d,j] * S[i,j]  -> [D,W] per (bc,head), into t0 ([bc,F,W])
        gemm_k<0,1,0,0><<<dim3(8,2,16),256>>>(v, s, t0, nullptr,
            Dd, Ww, Ww, Ww, Ww, Ww, Hh, BIGMOD,
            (long long)FW, DW, 4LL*FW, (long long)FW, (long long)FW, DW, 0, 1.f);

        // output projection + 1x1 channel conv + residual LN
        WGEMM(ow + lwF, t0, t1, ob + l*Cc*Ff, Ff, Ff, false);
        chanmix_k<<<EW,256>>>(t1, t0, ocw + l*Cc*Cc, ocb + l*Cc);
        lnres_k<<<LN_G,LN_B>>>(h, t0, n1w + l*Cc*Ff, n1b + l*Cc*Ff);

        // FFN
        WGEMM(f1w + (long long)l*Cc*EF*Ff, h, u, f1b + l*Cc*EF, EF, Ff, true);
        WGEMM(f2w + (long long)l*Cc*Ff*EF, u, t0, f2b + l*Cc*Ff, Ff, EF, false);
        lnres_k<<<LN_G,LN_B>>>(h, t0, n2w + l*Cc*Ff, n2b + l*Cc*Ff);
    }

    // --------- output channel mix ---------
    chanmix_k<<<EW,256>>>(h, (float*)d_out, out_w, nullptr);
}

// round 6
// speedup vs baseline: 2.6142x; 2.6142x over previous
#include <cuda_runtime.h>
#include <cuda_bf16.h>
#include <math.h>
#include <cstdint>

// Problem constants
#define Bn 2
#define Cc 2
#define Ff 1024
#define Ww 1024
#define Hh 4
#define Dd 256
#define EF 4096
#define Ll 15
#define NBn 3
#define BC 4              // B*C
#define FW (Ff*Ww)        // 1048576
#define WW (Ww*Ww)        // 1048576

// ---------------- scratch (device globals; no allocations) ----------------
__device__ float g_h [BC*FW];
__device__ float g_t0[BC*FW];
__device__ float g_t1[BC*FW];
__device__ float g_s [16*WW];                 // attention scores fp32 [bc,h,Wq,Wk]
__device__ float g_u [(size_t)BC*EF*Ww];      // FFN intermediate fp32 [bc,EF,W]

__device__ __nv_bfloat16 g_hTh[BC*FW], g_hTl[BC*FW];   // [bc,W,F] transposed activations
__device__ __nv_bfloat16 g_qTh[BC*FW], g_qTl[BC*FW];   // [bc,W,F] (also reused for attnT)
__device__ __nv_bfloat16 g_kTh[BC*FW], g_kTl[BC*FW];
__device__ __nv_bfloat16 g_vh [BC*FW], g_vl [BC*FW];   // V [bc,F,W]
__device__ __nv_bfloat16 g_sh [16*WW], g_sl [16*WW];   // softmax out bf16 split
__device__ __nv_bfloat16 g_uTh[(size_t)BC*Ww*EF], g_uTl[(size_t)BC*Ww*EF]; // [bc,W,EF]
__device__ __nv_bfloat16 g_wh [(size_t)Cc*EF*Ff], g_wl[(size_t)Cc*EF*Ff];  // weight split scratch

__device__ __forceinline__ float gelu_f(float x) {
    return 0.5f * x * (1.0f + erff(x * 0.70710678118654752f));
}

// ================= async-copy / mma.sync helpers =================
__device__ __forceinline__ uint32_t s2u(const void* p){
    uint32_t a;
    asm("{ .reg .u64 t; cvta.to.shared.u64 t, %1; cvt.u32.u64 %0, t; }" : "=r"(a) : "l"(p));
    return a;
}
__device__ __forceinline__ void cpa16(uint32_t dst, const void* src){
    asm volatile("cp.async.cg.shared.global [%0], [%1], 16;" :: "r"(dst), "l"(src));
}
__device__ __forceinline__ void cpa_commit(){ asm volatile("cp.async.commit_group;" ::: "memory"); }
template<int N> __device__ __forceinline__ void cpa_wait(){
    asm volatile("cp.async.wait_group %0;" :: "n"(N) : "memory");
}
__device__ __forceinline__ void ldm4(uint32_t& r0, uint32_t& r1, uint32_t& r2, uint32_t& r3, uint32_t a){
    asm volatile("ldmatrix.sync.aligned.m8n8.x4.shared.b16 {%0,%1,%2,%3}, [%4];"
                 : "=r"(r0), "=r"(r1), "=r"(r2), "=r"(r3) : "r"(a));
}
__device__ __forceinline__ void mma16816(float* c,
    uint32_t a0, uint32_t a1, uint32_t a2, uint32_t a3, uint32_t b0, uint32_t b1){
    asm volatile(
        "mma.sync.aligned.m16n8k16.row.col.f32.bf16.bf16.f32 "
        "{%0,%1,%2,%3}, {%4,%5,%6,%7}, {%8,%9}, {%0,%1,%2,%3};"
        : "+f"(c[0]), "+f"(c[1]), "+f"(c[2]), "+f"(c[3])
        : "r"(a0), "r"(a1), "r"(a2), "r"(a3), "r"(b0), "r"(b1));
}

// ================= split-bf16 tensor-core GEMM (mma.sync) =================
// C[m,n] = scale * sum_k A(m,k)*B(n,k) (+bias[m]) (optional GELU)
// A,B: bf16 hi/lo pairs, K-major rows (row strides lda/ldb elements).
// CTA tile 128(M) x 128(N), K chunk 64, 2-stage cp.async double buffer.
// Requires M%128==0, N%128==0, K%64==0 (all shapes here satisfy this).
#define KC 64
#define STG_BYTES 65536u       // Ah 16K | Al 16K | Bh 16K | Bl 16K
#define TG_SMEM 132096         // 2 stages + 1K alignment slack

__device__ __forceinline__ void load_tiles(
    uint32_t sb,
    const __nv_bfloat16* pAh, const __nv_bfloat16* pAl,
    const __nv_bfloat16* pBh, const __nv_bfloat16* pBl,
    int m0, int n0, int k0, int lda, int ldb, int tid)
{
    #pragma unroll
    for (int it = 0; it < 4; it++) {
        const int slot = tid + it*256;          // 0..1023 : 128 rows x 8 chunks
        const int r = slot >> 3, c = slot & 7;
        const uint32_t sw = (uint32_t)(r*128) + (uint32_t)((c ^ (r & 7)) * 16);
        const long long ga = (long long)(m0 + r)*lda + k0 + c*8;
        const long long gb = (long long)(n0 + r)*ldb + k0 + c*8;
        cpa16(sb +     0 + sw, pAh + ga);
        cpa16(sb + 16384 + sw, pAl + ga);
        cpa16(sb + 32768 + sw, pBh + gb);
        cpa16(sb + 49152 + sw, pBl + gb);
    }
}

template<int DOGELU, int HASBIAS>
__global__ __launch_bounds__(256, 1) void tgemm_k(
    const __nv_bfloat16* __restrict__ Agh, const __nv_bfloat16* __restrict__ Agl,
    const __nv_bfloat16* __restrict__ Bgh, const __nv_bfloat16* __restrict__ Bgl,
    float* __restrict__ Cg, const float* __restrict__ biasg,
    int K, int lda, int ldb, int ldc, int heads, int aMod,
    long long aSB, long long aSH, long long bSB, long long bSH,
    long long cSB, long long cSH, long long biasSB, float scale)
{
    extern __shared__ char dsm[];
    const uint32_t base = (s2u(dsm) + 1023u) & ~1023u;
    const int tid = threadIdx.x;
    const int lane = tid & 31;
    const int wid = tid >> 5;
    const int wm = wid >> 2, wn = wid & 3;      // 2 x 4 warp grid, warp tile 64x32

    const int z = blockIdx.z, bb = z / heads, hh = z % heads;
    const __nv_bfloat16* pAh = Agh + (long long)(bb % aMod)*aSB + (long long)hh*aSH;
    const __nv_bfloat16* pAl = Agl + (long long)(bb % aMod)*aSB + (long long)hh*aSH;
    const __nv_bfloat16* pBh = Bgh + (long long)bb*bSB + (long long)hh*bSH;
    const __nv_bfloat16* pBl = Bgl + (long long)bb*bSB + (long long)hh*bSH;
    float* C = Cg + (long long)bb*cSB + (long long)hh*cSH;
    const int m0 = blockIdx.y * 128;
    const int n0 = blockIdx.x * 128;

    float acc[4][4][4];
    #pragma unroll
    for (int i = 0; i < 4; i++)
        #pragma unroll
        for (int j = 0; j < 4; j++)
            #pragma unroll
            for (int r = 0; r < 4; r++) acc[i][j][r] = 0.f;

    const int NC = K / KC;
    load_tiles(base, pAh, pAl, pBh, pBl, m0, n0, 0, lda, ldb, tid);
    cpa_commit();
    if (NC > 1) {
        load_tiles(base + STG_BYTES, pAh, pAl, pBh, pBl, m0, n0, KC, lda, ldb, tid);
        cpa_commit();
    }

    #pragma unroll 1
    for (int c = 0; c < NC; c++) {
        const int s = c & 1;
        const uint32_t sb = base + (uint32_t)s * STG_BYTES;
        if (c + 1 < NC) cpa_wait<1>(); else cpa_wait<0>();
        __syncthreads();

        #pragma unroll
        for (int kk = 0; kk < 4; kk++) {        // 4 k16 steps per 64-chunk
            const int colc = kk*2 + (lane >> 4);      // 16B chunk index (pre-swizzle)
            uint32_t ah[4][4], al[4][4];
            #pragma unroll
            for (int mt = 0; mt < 4; mt++) {
                const int r = wm*64 + mt*16 + (lane & 15);
                const uint32_t ad = sb + (uint32_t)(r*128) + (uint32_t)((colc ^ (r & 7)) * 16);
                ldm4(ah[mt][0], ah[mt][1], ah[mt][2], ah[mt][3], ad);
                ldm4(al[mt][0], al[mt][1], al[mt][2], al[mt][3], ad + 16384);
            }
            uint32_t bh[2][4], bl[2][4];
            #pragma unroll
            for (int nt = 0; nt < 2; nt++) {
                const int r = wn*32 + nt*16 + (lane & 15);
                const uint32_t bd = sb + 32768 + (uint32_t)(r*128) + (uint32_t)((colc ^ (r & 7)) * 16);
                ldm4(bh[nt][0], bh[nt][1], bh[nt][2], bh[nt][3], bd);
                ldm4(bl[nt][0], bl[nt][1], bl[nt][2], bl[nt][3], bd + 16384);
            }
            #pragma unroll
            for (int mt = 0; mt < 4; mt++) {
                #pragma unroll
                for (int n8 = 0; n8 < 4; n8++) {
                    const int nt = n8 >> 1, j = n8 & 1;
                    float* cc = acc[mt][n8];
                    mma16816(cc, ah[mt][0], ah[mt][1], ah[mt][2], ah[mt][3], bh[nt][j], bh[nt][j+2]);
                    mma16816(cc, ah[mt][0], ah[mt][1], ah[mt][2], ah[mt][3], bl[nt][j], bl[nt][j+2]);
                    mma16816(cc, al[mt][0], al[mt][1], al[mt][2], al[mt][3], bh[nt][j], bh[nt][j+2]);
                }
            }
        }
        __syncthreads();
        if (c + 2 < NC) {
            load_tiles(base + (uint32_t)s * STG_BYTES, pAh, pAl, pBh, pBl,
                       m0, n0, (c + 2) * KC, lda, ldb, tid);
            cpa_commit();
        }
    }

    // epilogue: scale, +bias(row), optional GELU
    const float* bp = HASBIAS ? (biasg + (long long)(bb % aMod)*biasSB) : nullptr;
    #pragma unroll
    for (int mt = 0; mt < 4; mt++) {
        const int r0 = m0 + wm*64 + mt*16 + (lane >> 2);
        const int r1 = r0 + 8;
        const float bv0 = HASBIAS ? bp[r0] : 0.f;
        const float bv1 = HASBIAS ? bp[r1] : 0.f;
        #pragma unroll
        for (int n8 = 0; n8 < 4; n8++) {
            const int cn = n0 + wn*32 + n8*8 + (lane & 3)*2;
            float2 v0, v1;
            v0.x = acc[mt][n8][0]*scale + bv0;
            v0.y = acc[mt][n8][1]*scale + bv0;
            v1.x = acc[mt][n8][2]*scale + bv1;
            v1.y = acc[mt][n8][3]*scale + bv1;
            if (DOGELU) { v0.x = gelu_f(v0.x); v0.y = gelu_f(v0.y);
                          v1.x = gelu_f(v1.x); v1.y = gelu_f(v1.y); }
            *(float2*)&C[(long long)r0*ldc + cn] = v0;
            *(float2*)&C[(long long)r1*ldc + cn] = v1;
        }
    }
}

// ================= fp32 -> bf16 hi/lo splits =================
__device__ __forceinline__ void split2(float v, __nv_bfloat16& h, __nv_bfloat16& l){
    h = __float2bfloat16(v);
    l = __float2bfloat16(v - __bfloat162float(h));
}

__global__ __launch_bounds__(256) void split_k(
    const float* __restrict__ x, __nv_bfloat16* __restrict__ oh,
    __nv_bfloat16* __restrict__ ol, int n4)
{
    const int i = blockIdx.x * 256 + threadIdx.x;
    if (i >= n4) return;
    const float4 v = ((const float4*)x)[i];
    __nv_bfloat162 h0, h1, l0, l1;
    split2(v.x, h0.x, l0.x); split2(v.y, h0.y, l0.y);
    split2(v.z, h1.x, l1.x); split2(v.w, h1.y, l1.y);
    ((__nv_bfloat162*)oh)[i*2]   = h0; ((__nv_bfloat162*)oh)[i*2+1] = h1;
    ((__nv_bfloat162*)ol)[i*2]   = l0; ((__nv_bfloat162*)ol)[i*2+1] = l1;
}

// transpose+split: in [bc, R, W] fp32 -> out [bc, W, R] bf16 hi/lo
__global__ __launch_bounds__(256) void splitT_k(
    const float* __restrict__ x, __nv_bfloat16* __restrict__ oh,
    __nv_bfloat16* __restrict__ ol, int R)
{
    __shared__ float t[32][33];
    const int bc = blockIdx.z;
    const int w0 = blockIdx.x * 32, r0 = blockIdx.y * 32;
    const int tx = threadIdx.x, ty = threadIdx.y;     // (32,8)
    const float* xb = x + (size_t)bc * R * Ww;
    #pragma unroll
    for (int i = 0; i < 4; i++)
        t[ty + i*8][tx] = xb[(size_t)(r0 + ty + i*8) * Ww + w0 + tx];
    __syncthreads();
    __nv_bfloat16* ohb = oh + (size_t)bc * Ww * R;
    __nv_bfloat16* olb = ol + (size_t)bc * Ww * R;
    #pragma unroll
    for (int i = 0; i < 4; i++) {
        const float v = t[tx][ty + i*8];
        __nv_bfloat16 h, l; split2(v, h, l);
        const size_t o = (size_t)(w0 + ty + i*8) * R + r0 + tx;
        ohb[o] = h; olb[o] = l;
    }
}

// ---------------- conv 3x3 (pad 1), optional GELU ----------------
__global__ __launch_bounds__(256) void conv3x3_k(
    const float* __restrict__ x, float* __restrict__ y,
    const float* __restrict__ wt, const float* __restrict__ bs, int dogelu)
{
    const int t = blockIdx.x * 256 + threadIdx.x;
    const int wc = t & 1023;
    const int f  = (t >> 10) & 1023;
    const int co = (t >> 20) & 1;
    const int bb = t >> 21;
    float s = bs[co];
    #pragma unroll
    for (int ci = 0; ci < Cc; ci++) {
        const float* xp = x + ((size_t)(bb*Cc + ci)) * FW;
        const float* wp = wt + (co*Cc + ci) * 9;
        #pragma unroll
        for (int ky = 0; ky < 3; ky++) {
            const int ff = f + ky - 1;
            if ((unsigned)ff < (unsigned)Ff) {
                const float* row = xp + (size_t)ff * Ww;
                #pragma unroll
                for (int kx = 0; kx < 3; kx++) {
                    const int ww = wc + kx - 1;
                    if ((unsigned)ww < (unsigned)Ww) s = fmaf(row[ww], wp[ky*3+kx], s);
                }
            }
        }
    }
    if (dogelu) s = gelu_f(s);
    y[t] = s;
}

// ---------------- conv 1x7 along W (pad 3) ----------------
__global__ __launch_bounds__(256) void conv1x7_k(
    const float* __restrict__ x, float* __restrict__ y,
    const float* __restrict__ wt, const float* __restrict__ bs)
{
    const int t = blockIdx.x * 256 + threadIdx.x;
    const int wc = t & 1023;
    const int f  = (t >> 10) & 1023;
    const int co = (t >> 20) & 1;
    const int bb = t >> 21;
    float s = bs[co];
    #pragma unroll
    for (int ci = 0; ci < Cc; ci++) {
        const float* row = x + ((size_t)(bb*Cc + ci) * Ff + f) * Ww;
        const float* wp  = wt + (co*Cc + ci) * 7;
        #pragma unroll
        for (int j = 0; j < 7; j++) {
            const int ww = wc + j - 3;
            if ((unsigned)ww < (unsigned)Ww) s = fmaf(row[ww], wp[j], s);
        }
    }
    y[t] = s;
}

// ---------------- interleaved RoPE in place on [bc, F, W] ----------------
__global__ __launch_bounds__(256) void rope_k(float* __restrict__ p)
{
    const int t = blockIdx.x * 256 + threadIdx.x;      // BC*(F/2)*W
    const int wc = t & 1023;
    const int fp = (t >> 10) & 511;
    const int bc = t >> 19;
    const int tt = fp & 127;
    const float inv = expf(-(float)tt * (9.2103403719761836f / 128.f));
    const float ang = (float)wc * inv;
    float sn, cn; sincosf(ang, &sn, &cn);
    const size_t base = ((size_t)bc * Ff + 2*fp) * Ww + wc;
    const float x0 = p[base], x1 = p[base + Ww];
    p[base]      = x0*cn - x1*sn;
    p[base + Ww] = x1*cn + x0*sn;
}

// ---------------- row softmax -> bf16 hi/lo ----------------
__global__ __launch_bounds__(256) void softmax_k(
    const float* __restrict__ sp, __nv_bfloat16* __restrict__ oh,
    __nv_bfloat16* __restrict__ ol)
{
    const size_t row = blockIdx.x;
    const float* p = sp + row * Ww;
    const int t = threadIdx.x, lane = t & 31, wid = t >> 5;
    float4 v = ((const float4*)p)[t];
    float mx = fmaxf(fmaxf(v.x, v.y), fmaxf(v.z, v.w));
    #pragma unroll
    for (int o = 16; o > 0; o >>= 1) mx = fmaxf(mx, __shfl_xor_sync(0xffffffffu, mx, o));
    __shared__ float red[8];
    if (lane == 0) red[wid] = mx;
    __syncthreads();
    mx = red[0];
    #pragma unroll
    for (int i = 1; i < 8; i++) mx = fmaxf(mx, red[i]);
    __syncthreads();
    v.x = expf(v.x - mx); v.y = expf(v.y - mx); v.z = expf(v.z - mx); v.w = expf(v.w - mx);
    float sm = v.x + v.y + v.z + v.w;
    #pragma unroll
    for (int o = 16; o > 0; o >>= 1) sm += __shfl_xor_sync(0xffffffffu, sm, o);
    if (lane == 0) red[wid] = sm;
    __syncthreads();
    sm = red[0]+red[1]+red[2]+red[3]+red[4]+red[5]+red[6]+red[7];
    const float r = 1.f / sm;
    v.x *= r; v.y *= r; v.z *= r; v.w *= r;
    __nv_bfloat162 h0, h1, l0, l1;
    split2(v.x, h0.x, l0.x); split2(v.y, h0.y, l0.y);
    split2(v.z, h1.x, l1.x); split2(v.w, h1.y, l1.y);
    ((__nv_bfloat162*)(oh + row*Ww))[t*2]   = h0;
    ((__nv_bfloat162*)(oh + row*Ww))[t*2+1] = h1;
    ((__nv_bfloat162*)(ol + row*Ww))[t*2]   = l0;
    ((__nv_bfloat162*)(ol + row*Ww))[t*2+1] = l1;
}

// ---------------- residual + LayerNorm over F, h <- LN(h+z) ----------------
__global__ __launch_bounds__(512) void lnres_k(
    float* __restrict__ h, const float* __restrict__ z,
    const float* __restrict__ g, const float* __restrict__ b)
{
    const int tx = threadIdx.x, ty = threadIdx.y;
    const int wc = blockIdx.x * 32 + tx;
    const int bc = blockIdx.y;
    const int c  = bc & 1;
    float* hp = h + (size_t)bc * FW + wc;
    const float* zp = z + (size_t)bc * FW + wc;
    float sum = 0.f, sq = 0.f;
    for (int f = ty; f < Ff; f += 16) {
        const float v = hp[(size_t)f * Ww] + zp[(size_t)f * Ww];
        sum += v; sq += v * v;
    }
    __shared__ float s1[16][32], s2[16][32];
    __shared__ float smu[32], srs[32];
    s1[ty][tx] = sum; s2[ty][tx] = sq;
    __syncthreads();
    if (ty == 0) {
        float a = 0.f, q = 0.f;
        #pragma unroll
        for (int r = 0; r < 16; r++) { a += s1[r][tx]; q += s2[r][tx]; }
        const float mu = a * (1.f / Ff);
        const float var = q * (1.f / Ff) - mu * mu;
        smu[tx] = mu; srs[tx] = rsqrtf(var + 1e-5f);
    }
    __syncthreads();
    const float mu = smu[tx], rs = srs[tx];
    for (int f = ty; f < Ff; f += 16) {
        const float v = hp[(size_t)f * Ww] + zp[(size_t)f * Ww];
        hp[(size_t)f * Ww] = (v - mu) * rs * g[c*Ff + f] + b[c*Ff + f];
    }
}

// ---------------- 2-channel mix (1x1 conv / output projection) ----------------
__global__ __launch_bounds__(256) void chanmix_k(
    const float* __restrict__ in, float* __restrict__ out,
    const float* __restrict__ m, const float* __restrict__ bs)
{
    const int t = blockIdx.x * 256 + threadIdx.x;
    const int pos = t & (FW - 1);
    const int co  = (t >> 20) & 1;
    const int bb  = t >> 21;
    float s = bs ? bs[co] : 0.f;
    s = fmaf(in[(size_t)(bb*Cc + 0) * FW + pos], m[co*Cc + 0], s);
    s = fmaf(in[(size_t)(bb*Cc + 1) * FW + pos], m[co*Cc + 1], s);
    out[t] = s;
}

// ---------------- launch ----------------
extern "C" void kernel_launch(void* const* d_in, const int* in_sizes, int n_in,
                              void* d_out, int out_size)
{
    (void)in_sizes; (void)n_in; (void)out_size;
    const float* x       = (const float*)d_in[0];
    const float* enc_c1w = (const float*)d_in[1];
    const float* enc_c1b = (const float*)d_in[2];
    const float* enc_c2w = (const float*)d_in[3];
    const float* enc_c2b = (const float*)d_in[4];
    const float* enc_nw  = (const float*)d_in[5];
    const float* enc_nb  = (const float*)d_in[6];
    const float* qw  = (const float*)d_in[7];
    const float* qb  = (const float*)d_in[8];
    const float* qcw = (const float*)d_in[9];
    const float* qcb = (const float*)d_in[10];
    const float* kw  = (const float*)d_in[11];
    const float* kb  = (const float*)d_in[12];
    const float* kcw = (const float*)d_in[13];
    const float* kcb = (const float*)d_in[14];
    const float* vw  = (const float*)d_in[15];
    const float* vb  = (const float*)d_in[16];
    const float* vcw = (const float*)d_in[17];
    const float* vcb = (const float*)d_in[18];
    const float* ow  = (const float*)d_in[19];
    const float* ob  = (const float*)d_in[20];
    const float* ocw = (const float*)d_in[21];
    const float* ocb = (const float*)d_in[22];
    const float* n1w = (const float*)d_in[23];
    const float* n1b = (const float*)d_in[24];
    const float* f1w = (const float*)d_in[25];
    const float* f1b = (const float*)d_in[26];
    const float* f2w = (const float*)d_in[27];
    const float* f2b = (const float*)d_in[28];
    const float* n2w = (const float*)d_in[29];
    const float* n2b = (const float*)d_in[30];
    const float* out_w = (const float*)d_in[31];

    float *h, *t0, *t1, *s, *u;
    __nv_bfloat16 *hTh,*hTl,*qTh,*qTl,*kTh,*kTl,*vh,*vl,*sh,*sl,*uTh,*uTl,*wh,*wl;
    cudaGetSymbolAddress((void**)&h,  g_h);
    cudaGetSymbolAddress((void**)&t0, g_t0);
    cudaGetSymbolAddress((void**)&t1, g_t1);
    cudaGetSymbolAddress((void**)&s,  g_s);
    cudaGetSymbolAddress((void**)&u,  g_u);
    cudaGetSymbolAddress((void**)&hTh, g_hTh); cudaGetSymbolAddress((void**)&hTl, g_hTl);
    cudaGetSymbolAddress((void**)&qTh, g_qTh); cudaGetSymbolAddress((void**)&qTl, g_qTl);
    cudaGetSymbolAddress((void**)&kTh, g_kTh); cudaGetSymbolAddress((void**)&kTl, g_kTl);
    cudaGetSymbolAddress((void**)&vh,  g_vh);  cudaGetSymbolAddress((void**)&vl,  g_vl);
    cudaGetSymbolAddress((void**)&sh,  g_sh);  cudaGetSymbolAddress((void**)&sl,  g_sl);
    cudaGetSymbolAddress((void**)&uTh, g_uTh); cudaGetSymbolAddress((void**)&uTl, g_uTl);
    cudaGetSymbolAddress((void**)&wh,  g_wh);  cudaGetSymbolAddress((void**)&wl,  g_wl);

    cudaFuncSetAttribute(tgemm_k<0,0>, cudaFuncAttributeMaxDynamicSharedMemorySize, TG_SMEM);
    cudaFuncSetAttribute(tgemm_k<0,1>, cudaFuncAttributeMaxDynamicSharedMemorySize, TG_SMEM);
    cudaFuncSetAttribute(tgemm_k<1,1>, cudaFuncAttributeMaxDynamicSharedMemorySize, TG_SMEM);

    const int EW = 16384;
    const dim3 LN_G(Ww/32, BC), LN_B(32, 16);
    const int BIG = 1 << 24;

    cudaMemcpyAsync(h, x, sizeof(float) * (size_t)BC * FW, cudaMemcpyDeviceToDevice, 0);

    // weight-style linear: C[bc, M, W] = W[c, M, K] @ XT[bc, W, K]^T + bias
    auto WG = [&](const __nv_bfloat16* Ah, const __nv_bfloat16* Al,
                  const __nv_bfloat16* Bh, const __nv_bfloat16* Bl,
                  float* Cx, const float* bias, int M, int K, long long cRow, bool gelu) {
        dim3 grid(Ww/128, M/128, BC);
        if (gelu)
            tgemm_k<1,1><<<grid,256,TG_SMEM>>>(Ah, Al, Bh, Bl, Cx, bias,
                K, K, K, Ww, 1, Cc, (long long)M*K, 0, (long long)Ww*K, 0,
                cRow, 0, (long long)M, 1.f);
        else
            tgemm_k<0,1><<<grid,256,TG_SMEM>>>(Ah, Al, Bh, Bl, Cx, bias,
                K, K, K, Ww, 1, Cc, (long long)M*K, 0, (long long)Ww*K, 0,
                cRow, 0, (long long)M, 1.f);
    };

    // --------- FrameEncoder: 3 ResBlocks ---------
    for (int nb = 0; nb < NBn; nb++) {
        conv3x3_k<<<EW,256>>>(h,  t0, enc_c1w + nb*Cc*Cc*9, enc_c1b + nb*Cc, 1);
        conv3x3_k<<<EW,256>>>(t0, t1, enc_c2w + nb*Cc*Cc*9, enc_c2b + nb*Cc, 0);
        lnres_k<<<LN_G,LN_B>>>(h, t1, enc_nw + nb*Cc*Ff, enc_nb + nb*Cc*Ff);
    }

    const dim3 ST_B(32, 8);
    const dim3 ST_F(Ww/32, Ff/32, BC);      // transpose-split R=F
    const dim3 ST_E(Ww/32, EF/32, BC);      // transpose-split R=EF

    // --------- Transformer layers ---------
    for (int l = 0; l < Ll; l++) {
        const long long lwF = (long long)l * Cc * Ff * Ff;
        const long long lwE = (long long)l * Cc * EF * Ff;

        splitT_k<<<ST_F,ST_B>>>(h, hTh, hTl, Ff);   // [bc,W,F]

        // Q
        split_k<<<2048,256>>>(qw + lwF, wh, wl, Cc*Ff*Ff/4);
        WG(wh, wl, hTh, hTl, t0, qb + l*Cc*Ff, Ff, Ff, (long long)FW, false);
        conv1x7_k<<<EW,256>>>(t0, t1, qcw + l*Cc*Cc*7, qcb + l*Cc);
        rope_k<<<8192,256>>>(t1);
        splitT_k<<<ST_F,ST_B>>>(t1, qTh, qTl, Ff);
        // K
        split_k<<<2048,256>>>(kw + lwF, wh, wl, Cc*Ff*Ff/4);
        WG(wh, wl, hTh, hTl, t0, kb + l*Cc*Ff, Ff, Ff, (long long)FW, false);
        conv1x7_k<<<EW,256>>>(t0, t1, kcw + l*Cc*Cc*7, kcb + l*Cc);
        rope_k<<<8192,256>>>(t1);
        splitT_k<<<ST_F,ST_B>>>(t1, kTh, kTl, Ff);
        // V
        split_k<<<2048,256>>>(vw + lwF, wh, wl, Cc*Ff*Ff/4);
        WG(wh, wl, hTh, hTl, t0, vb + l*Cc*Ff, Ff, Ff, (long long)FW, false);
        conv1x7_k<<<EW,256>>>(t0, t1, vcw + l*Cc*Cc*7, vcb + l*Cc);
        split_k<<<4096,256>>>(t1, vh, vl, BC*FW/4);

        // scores[z=bc*4+h, q, k] = Q[q,:] . K[k,:] / 32
        tgemm_k<0,0><<<dim3(Ww/128, Ww/128, 16),256,TG_SMEM>>>(
            qTh, qTl, kTh, kTl, s, nullptr,
            Dd, Ff, Ff, Ww, Hh, BIG,
            (long long)FW, (long long)Dd, (long long)FW, (long long)Dd,
            4LL*WW, (long long)WW, 0, 0.03125f);
        softmax_k<<<16*1024,256>>>(s, sh, sl);
        // attnT[bc, q, h*256+d] = sum_j S[q,j] V[h*256+d, j]
        tgemm_k<0,0><<<dim3(Dd/128, Ww/128, 16),256,TG_SMEM>>>(
            sh, sl, vh, vl, t0, nullptr,
            Ww, Ww, Ww, Ff, Hh, BIG,
            4LL*WW, (long long)WW, (long long)FW, (long long)Dd*Ww,
            (long long)FW, (long long)Dd, 0, 1.f);
        split_k<<<4096,256>>>(t0, qTh, qTl, BC*FW/4);   // reuse qT as attnT split

        // output projection + 1x1 channel conv + residual LN
        split_k<<<2048,256>>>(ow + lwF, wh, wl, Cc*Ff*Ff/4);
        WG(wh, wl, qTh, qTl, t1, ob + l*Cc*Ff, Ff, Ff, (long long)FW, false);
        chanmix_k<<<EW,256>>>(t1, t0, ocw + l*Cc*Cc, ocb + l*Cc);
        lnres_k<<<LN_G,LN_B>>>(h, t0, n1w + l*Cc*Ff, n1b + l*Cc*Ff);

        // FFN
        splitT_k<<<ST_F,ST_B>>>(h, hTh, hTl, Ff);
        split_k<<<8192,256>>>(f1w + lwE, wh, wl, Cc*EF*Ff/4);
        WG(wh, wl, hTh, hTl, u, f1b + l*Cc*EF, EF, Ff, (long long)EF*Ww, true);
        splitT_k<<<ST_E,ST_B>>>(u, uTh, uTl, EF);
        split_k<<<8192,256>>>(f2w + lwE, wh, wl, Cc*Ff*EF/4);
        WG(wh, wl, uTh, uTl, t0, f2b + l*Cc*Ff, Ff, EF, (long long)FW, false);
        lnres_k<<<LN_G,LN_B>>>(h, t0, n2w + l*Cc*Ff, n2b + l*Cc*Ff);
    }

    // --------- output channel mix ---------
    chanmix_k<<<EW,256>>>(h, (float*)d_out, out_w, nullptr);
}